// round 11
// baseline (speedup 1.0000x reference)
#include <cuda_runtime.h>
#include <cuda_fp16.h>
#include <math.h>

#define B_    4096
#define INF   64
#define KM    16
#define SQ    32
#define HH    64
#define NMD   48
#define NH    512
#define NT    1024
#define PMAXF 8.0f

#define ROWS  32
#define RSTR  36          // xs transposed stride
#define ASTR  520         // a1 fp16 row stride (1040B, ldmatrix conflict-free)
#define NST   8           // cp.async B pipeline depth
#define GRID  128

// Scratch (no allocations allowed)
__device__ float g_tab[KM * NT];
__device__ __align__(16) __half w2f_frag[NH * NH];   // uint4 slot = kf*1024 + warp*32 + lane
__device__ unsigned long long g_bar = 0ULL;          // monotonic global barrier counter

// ---------------------------------------------------------------------------
// helpers
// ---------------------------------------------------------------------------
__device__ __forceinline__ unsigned long long pack2(float lo, float hi) {
    unsigned long long r;
    asm("mov.b64 %0, {%1, %2};" : "=l"(r) : "f"(lo), "f"(hi));
    return r;
}
__device__ __forceinline__ float2 unpack2(unsigned long long v) {
    float2 r;
    asm("mov.b64 {%0, %1}, %2;" : "=f"(r.x), "=f"(r.y) : "l"(v));
    return r;
}
__device__ __forceinline__ void fma2(unsigned long long& d,
                                     unsigned long long a,
                                     unsigned long long b) {
    asm("fma.rn.f32x2 %0, %1, %2, %0;" : "+l"(d) : "l"(a), "l"(b));
}
__device__ __forceinline__ void add2(unsigned long long& d, unsigned long long a) {
    asm("add.rn.f32x2 %0, %0, %1;" : "+l"(d) : "l"(a));
}
__device__ __forceinline__ unsigned smem_u32(const void* p) {
    unsigned r;
    asm("{ .reg .u64 t; cvta.to.shared.u64 t, %1; cvt.u32.u64 %0, t; }"
        : "=r"(r) : "l"(p));
    return r;
}
__device__ __forceinline__ void ldsm_x4(unsigned& r0, unsigned& r1,
                                        unsigned& r2, unsigned& r3, unsigned addr) {
    asm volatile("ldmatrix.sync.aligned.m8n8.x4.shared.b16 {%0,%1,%2,%3}, [%4];"
                 : "=r"(r0), "=r"(r1), "=r"(r2), "=r"(r3) : "r"(addr));
}
__device__ __forceinline__ void mma_f16(float* c, const unsigned* a, const unsigned* b) {
    asm volatile(
        "mma.sync.aligned.m16n8k16.row.col.f32.f16.f16.f32 "
        "{%0,%1,%2,%3}, {%4,%5,%6,%7}, {%8,%9}, {%0,%1,%2,%3};"
        : "+f"(c[0]), "+f"(c[1]), "+f"(c[2]), "+f"(c[3])
        : "r"(a[0]), "r"(a[1]), "r"(a[2]), "r"(a[3]), "r"(b[0]), "r"(b[1]));
}
__device__ __forceinline__ void cp16(unsigned saddr, const void* gptr) {
    asm volatile("cp.async.cg.shared.global [%0], [%1], 16;"
                 :: "r"(saddr), "l"(gptr) : "memory");
}
__device__ __forceinline__ void cp_commit() {
    asm volatile("cp.async.commit_group;" ::: "memory");
}
template <int N>
__device__ __forceinline__ void cp_wait() {
    asm volatile("cp.async.wait_group %0;" :: "n"(N) : "memory");
}

// ---------------------------------------------------------------------------
// MEGA kernel: phase A (prep + table build on all SMs) -> global barrier ->
// phase B (mono || layer1, then fp16-MMA layer2 with cp.async B pipe).
// Grid 128 x 1024 threads, 1 block/SM (smem-bound) => all co-resident.
// ---------------------------------------------------------------------------
__global__ void __launch_bounds__(1024, 1) mega_kernel(
    const float* __restrict__ X,   const float* __restrict__ wlin,
    const float* __restrict__ w1,  const float* __restrict__ b1,
    const float* __restrict__ b2,  const float* __restrict__ w3,
    const float* __restrict__ b3,  const float* __restrict__ w2full,
    const float* __restrict__ mw1, const float* __restrict__ mb1,
    const float* __restrict__ mw2, const float* __restrict__ mb2,
    const float* __restrict__ mw3, const float* __restrict__ mb3,
    float* __restrict__ out)
{
    extern __shared__ float sm[];
    const int tid  = threadIdx.x;
    const int warp = tid >> 5;
    const int lane = tid & 31;

    // ================= PHASE A: prep + table build =================
    {
        float* s_w2  = sm;            // [64*64]
        float* s_w1v = sm + HH * HH;  // [64] x4 vectors
        float* s_b1v = s_w1v + HH;
        float* s_b2v = s_b1v + HH;
        float* s_w3v = s_b2v + HH;

        // --- prep: 256 slots/block of w2 -> fp16 MMA-frag order ---
        if (tid < 256) {
            int t  = blockIdx.x * 256 + tid;     // 32768 slots total
            int pl = t & 31;
            int pw = (t >> 5) & 31;
            int kf = t >> 10;
            int kb = kf * 16 + (pl & 3) * 2;
            uint4 st;
            unsigned* sp = (unsigned*)&st;
#pragma unroll
            for (int nf = 0; nf < 2; nf++) {
                int j = pw * 16 + nf * 8 + (pl >> 2);
                float v00 = __ldg(w2full + (kb + 0) * NH + j);
                float v01 = __ldg(w2full + (kb + 1) * NH + j);
                float v10 = __ldg(w2full + (kb + 8) * NH + j);
                float v11 = __ldg(w2full + (kb + 9) * NH + j);
                __half2 q0 = __floats2half2_rn(v00, v01);
                __half2 q1 = __floats2half2_rn(v10, v11);
                sp[nf * 2 + 0] = *(unsigned*)&q0;
                sp[nf * 2 + 1] = *(unsigned*)&q1;
            }
            ((uint4*)w2f_frag)[t] = st;
        }

        // --- table: block covers 128 entries of k = blockIdx>>3, 8 thr/entry ---
        int k = blockIdx.x >> 3;
        ((float4*)s_w2)[tid] = ((const float4*)(mw2 + k * HH * HH))[tid];
        if (tid < HH) {
            s_w1v[tid] = mw1[k * HH + tid];
            s_b1v[tid] = mb1[k * HH + tid];
            s_b2v[tid] = mb2[k * HH + tid];
            s_w3v[tid] = mw3[k * HH + tid];
        }
        __syncthreads();

        int i  = (blockIdx.x & 7) * 128 + (tid >> 3);
        int jh = tid & 1;              // j-half
        int hq = (tid >> 1) & 3;       // h-quadrant
        float p = -PMAXF + (2.f * PMAXF / (NT - 1)) * (float)i;

        float h1v[16];
#pragma unroll
        for (int hh = 0; hh < 16; hh++)
            h1v[hh] = tanhf(fmaf(p, s_w1v[hq * 16 + hh], s_b1v[hq * 16 + hh]));

        unsigned long long acc[16];
#pragma unroll
        for (int q = 0; q < 16; q++) acc[q] = 0ull;
#pragma unroll
        for (int hh = 0; hh < 16; hh++) {
            int h = hq * 16 + hh;
            unsigned long long ad = pack2(h1v[hh], h1v[hh]);
            const ulonglong2* wr = (const ulonglong2*)&s_w2[h * HH + jh * 32];
#pragma unroll
            for (int q = 0; q < 8; q++) {
                ulonglong2 wv = wr[q];
                fma2(acc[2 * q],     wv.x, ad);
                fma2(acc[2 * q + 1], wv.y, ad);
            }
        }
        // combine across h-quadrants (lanes xor 2, xor 4 within 8-lane groups)
#pragma unroll
        for (int q = 0; q < 16; q++) {
            unsigned long long o = __shfl_xor_sync(0xffffffffu, acc[q], 2);
            add2(acc[q], o);
            o = __shfl_xor_sync(0xffffffffu, acc[q], 4);
            add2(acc[q], o);
        }
        // outer: each thread finishes 8 of its jh-half's 32 columns
        float z = 0.f;
#pragma unroll
        for (int q = 0; q < 4; q++) {
            int jl = jh * 32 + hq * 8 + 2 * q;
            float2 v = unpack2(acc[hq * 4 + q]);
            z = fmaf(s_w3v[jl],     tanhf(v.x + s_b2v[jl]),     z);
            z = fmaf(s_w3v[jl + 1], tanhf(v.y + s_b2v[jl + 1]), z);
        }
        z += __shfl_xor_sync(0xffffffffu, z, 1);
        z += __shfl_xor_sync(0xffffffffu, z, 2);
        z += __shfl_xor_sync(0xffffffffu, z, 4);
        if ((tid & 7) == 0) {
            z += __ldg(mb3 + k);
            g_tab[k * NT + i] = fmaxf(z, 0.f) + log1pf(expf(-fabsf(z)));
        }
    }

    // ================= GLOBAL BARRIER (monotonic, replay-safe) ============
    __threadfence();
    __syncthreads();
    if (tid == 0) {
        unsigned long long old = atomicAdd(&g_bar, 1ULL);
        unsigned long long target = (old / (unsigned long long)GRID + 1ULL)
                                  * (unsigned long long)GRID;
        while (*((volatile unsigned long long*)&g_bar) < target) { }
    }
    __syncthreads();
    __threadfence();

    // ================= PHASE B: fused model eval =================
    uint4*  bstage = (uint4*)sm;                          // [NST][32][32] uint4
    __half* a1f    = (__half*)(bstage + NST * 32 * 32);   // [32][ASTR]
    float*  xs     = (float*)(a1f + ROWS * ASTR);         // [NMD][RSTR]
    float*  wpart  = xs + NMD * RSTR;                     // [32][32]
    float*  mono_s = wpart + 32 * 32;                     // [32]
    const int b0 = blockIdx.x * ROWS;

    // prime B pipeline (fills during mono/layer1)
    const uint4* bgm = (const uint4*)w2f_frag + warp * 32 + lane;
    const unsigned bst_u = smem_u32(bstage) + (warp * 32 + lane) * 16;
#pragma unroll
    for (int s = 0; s < NST - 1; s++) {
        cp16(bst_u + s * 16384, bgm + s * 1024);
        cp_commit();
    }

    if (warp < 16) {
        // ---- stage xs, then layer 1 (warps 0-15) ----
        for (int idx = tid; idx < ROWS * NMD; idx += 512) {
            int r = idx / NMD, ii = idx % NMD;
            xs[ii * RSTR + r] = X[(b0 + r) * INF + KM + ii];
        }
        asm volatile("bar.sync 1, 512;" ::: "memory");

        const int c = tid;           // 0..511: one output col, all 32 rows
        unsigned long long acc[16];
#pragma unroll
        for (int rp = 0; rp < 16; rp++) acc[rp] = 0ull;
        const float* wp = w1 + c;
#pragma unroll 4
        for (int i = 0; i < NMD; i++) {
            float wv = wp[i * NH];
            unsigned long long wd = pack2(wv, wv);
            const ulonglong2* ap = (const ulonglong2*)(xs + i * RSTR);
#pragma unroll
            for (int q = 0; q < 8; q++) {
                ulonglong2 a = ap[q];
                fma2(acc[2 * q],     a.x, wd);
                fma2(acc[2 * q + 1], a.y, wd);
            }
        }
        float bv = b1[c];
#pragma unroll
        for (int rp = 0; rp < 16; rp++) {
            float2 v = unpack2(acc[rp]);
            a1f[(2 * rp) * ASTR + c]     = __float2half_rn(fmaxf(v.x + bv, 0.f));
            a1f[(2 * rp + 1) * ASTR + c] = __float2half_rn(fmaxf(v.y + bv, 0.f));
        }
    } else {
        // ---- mono term (warps 16-31): one (row, k) per thread ----
        int t2 = tid - 512;
        int r  = t2 >> 4;
        int kk = t2 & 15;
        const float scale = (float)(NT - 1) / (2.f * PMAXF);
        float x = __ldg(X + (b0 + r) * INF + kk);
        const float* tk = g_tab + kk * NT;
        float acc = 0.f;
#pragma unroll
        for (int s = 0; s < SQ; s++) {
            float t = (float)s * (1.f / (SQ - 1));
            float f = (x * t + PMAXF) * scale;
            f = fminf(fmaxf(f, 0.f), (float)(NT - 1) - 1e-3f);
            int i0 = (int)f;
            float fr = f - (float)i0;
            float g0 = tk[i0];
            float g1 = tk[i0 + 1];
            acc += fmaf(fr, g1 - g0, g0);
        }
        float part = acc * (1.f / SQ) * x * __ldg(wlin + kk);
#pragma unroll
        for (int off = 8; off; off >>= 1)
            part += __shfl_down_sync(0xffffffffu, part, off, 16);
        if ((t2 & 15) == 0) mono_s[r] = part;
    }
    __syncthreads();

    // ---- layer 2: fp16 MMA; B from smem ring, A ldsm double-buffered ----
    {
        float acc[2][2][4];
#pragma unroll
        for (int m = 0; m < 2; m++)
#pragma unroll
            for (int nf = 0; nf < 2; nf++)
#pragma unroll
                for (int e = 0; e < 4; e++) acc[m][nf][e] = 0.f;

        const unsigned a1_u = smem_u32(a1f);
        const int arow  = lane & 15;
        const int acol8 = (lane >> 4) * 8;
        const uint4* bsm = bstage + warp * 32 + lane;

        unsigned a[2][2][4];
#pragma unroll
        for (int m = 0; m < 2; m++) {
            unsigned off = ((m * 16 + arow) * ASTR + acol8) * 2;
            ldsm_x4(a[0][m][0], a[0][m][1], a[0][m][2], a[0][m][3], a1_u + off);
        }

        for (int kf = 0; kf < 32; kf++) {
            int cur = kf & 1, nxt = cur ^ 1;
            int sl = kf + NST - 1;
            if (sl < 32) cp16(bst_u + (sl & (NST - 1)) * 16384, bgm + sl * 1024);
            cp_commit();
            if (kf + 1 < 32) {
#pragma unroll
                for (int m = 0; m < 2; m++) {
                    unsigned off = ((m * 16 + arow) * ASTR + (kf + 1) * 16 + acol8) * 2;
                    ldsm_x4(a[nxt][m][0], a[nxt][m][1], a[nxt][m][2], a[nxt][m][3],
                            a1_u + off);
                }
            }
            cp_wait<NST - 1>();
            uint4 bq = bsm[(kf & (NST - 1)) * 1024];
            unsigned bfr[2][2] = {{bq.x, bq.y}, {bq.z, bq.w}};
#pragma unroll
            for (int m = 0; m < 2; m++)
#pragma unroll
                for (int nf = 0; nf < 2; nf++)
                    mma_f16(acc[m][nf], a[cur][m], bfr[nf]);
        }

        // epilogue: relu(acc + b2) . w3 -> per-row partials (16-col slice)
#pragma unroll
        for (int m = 0; m < 2; m++) {
            float p0 = 0.f, p1 = 0.f;
#pragma unroll
            for (int nf = 0; nf < 2; nf++) {
                int col = warp * 16 + nf * 8 + (lane & 3) * 2;
                float2 b2v = *(const float2*)(b2 + col);
                float2 w3v = *(const float2*)(w3 + col);
                p0 = fmaf(fmaxf(acc[m][nf][0] + b2v.x, 0.f), w3v.x, p0);
                p0 = fmaf(fmaxf(acc[m][nf][1] + b2v.y, 0.f), w3v.y, p0);
                p1 = fmaf(fmaxf(acc[m][nf][2] + b2v.x, 0.f), w3v.x, p1);
                p1 = fmaf(fmaxf(acc[m][nf][3] + b2v.y, 0.f), w3v.y, p1);
            }
            p0 += __shfl_xor_sync(0xffffffffu, p0, 1);
            p0 += __shfl_xor_sync(0xffffffffu, p0, 2);
            p1 += __shfl_xor_sync(0xffffffffu, p1, 1);
            p1 += __shfl_xor_sync(0xffffffffu, p1, 2);
            if ((lane & 3) == 0) {
                int r0 = m * 16 + (lane >> 2);
                wpart[warp * 32 + r0]     = p0;
                wpart[warp * 32 + r0 + 8] = p1;
            }
        }
    }
    __syncthreads();

    // ---- final: sum 32 warp slices + bias + mono ----
    if (tid < ROWS) {
        float s = 0.f;
#pragma unroll
        for (int w = 0; w < 32; w++) s += wpart[w * 32 + tid];
        out[b0 + tid] = s + __ldg(b3) + mono_s[tid];
    }
}

// ---------------------------------------------------------------------------
extern "C" void kernel_launch(void* const* d_in, const int* in_sizes, int n_in,
                              void* d_out, int out_size)
{
    const float* x    = (const float*)d_in[0];
    const float* mw1  = (const float*)d_in[1];
    const float* mb1  = (const float*)d_in[2];
    const float* mw2  = (const float*)d_in[3];
    const float* mb2  = (const float*)d_in[4];
    const float* mw3  = (const float*)d_in[5];
    const float* mb3  = (const float*)d_in[6];
    const float* wlin = (const float*)d_in[7];
    const float* nw1  = (const float*)d_in[8];
    const float* nb1  = (const float*)d_in[9];
    const float* nw2  = (const float*)d_in[10];
    const float* nb2  = (const float*)d_in[11];
    const float* nw3  = (const float*)d_in[12];
    const float* nb3  = (const float*)d_in[13];
    float* out = (float*)d_out;

    int smem = NST * 32 * 32 * 16
             + ROWS * ASTR * (int)sizeof(__half)
             + (NMD * RSTR + 32 * 32 + 32) * (int)sizeof(float);   // ~175.5 KB
    cudaFuncSetAttribute(mega_kernel, cudaFuncAttributeMaxDynamicSharedMemorySize, smem);

    mega_kernel<<<GRID, 1024, smem>>>(x, wlin, nw1, nb1, nb2, nw3, nb3, nw2,
                                      mw1, mb1, mw2, mb2, mw3, mb3, out);
}

// round 14
// speedup vs baseline: 2.8648x; 2.8648x over previous
#include <cuda_runtime.h>
#include <cuda_fp16.h>
#include <math.h>

#define B_    4096
#define INF   64
#define KM    16
#define SQ    32
#define HH    64
#define NMD   48
#define NH    512
#define NT    1024
#define PMAXF 8.0f

#define ROWS  32
#define XSTR  56          // xs fp16 row stride (112B rows)
#define ASTR  520         // a1 fp16 row stride (1040B, ldmatrix conflict-free)
#define NST   8           // cp.async B pipeline depth

// Scratch (no allocations allowed)
__device__ float g_tab[KM * NT];
__device__ __align__(16) __half w2f_frag[NH * NH];       // uint4 slot = kf*1024 + w*32 + lane
__device__ __align__(16) __half w1f_frag[3 * 16 * NH];   // layer-1 B frags, kf<3

// ---------------------------------------------------------------------------
// helpers
// ---------------------------------------------------------------------------
__device__ __forceinline__ unsigned long long pack2(float lo, float hi) {
    unsigned long long r;
    asm("mov.b64 %0, {%1, %2};" : "=l"(r) : "f"(lo), "f"(hi));
    return r;
}
__device__ __forceinline__ float2 unpack2(unsigned long long v) {
    float2 r;
    asm("mov.b64 {%0, %1}, %2;" : "=f"(r.x), "=f"(r.y) : "l"(v));
    return r;
}
__device__ __forceinline__ void fma2(unsigned long long& d,
                                     unsigned long long a,
                                     unsigned long long b) {
    asm("fma.rn.f32x2 %0, %1, %2, %0;" : "+l"(d) : "l"(a), "l"(b));
}
__device__ __forceinline__ unsigned smem_u32(const void* p) {
    unsigned r;
    asm("{ .reg .u64 t; cvta.to.shared.u64 t, %1; cvt.u32.u64 %0, t; }"
        : "=r"(r) : "l"(p));
    return r;
}
__device__ __forceinline__ void ldsm_x4(unsigned& r0, unsigned& r1,
                                        unsigned& r2, unsigned& r3, unsigned addr) {
    asm volatile("ldmatrix.sync.aligned.m8n8.x4.shared.b16 {%0,%1,%2,%3}, [%4];"
                 : "=r"(r0), "=r"(r1), "=r"(r2), "=r"(r3) : "r"(addr));
}
__device__ __forceinline__ void mma_f16(float* c, const unsigned* a, const unsigned* b) {
    asm volatile(
        "mma.sync.aligned.m16n8k16.row.col.f32.f16.f16.f32 "
        "{%0,%1,%2,%3}, {%4,%5,%6,%7}, {%8,%9}, {%0,%1,%2,%3};"
        : "+f"(c[0]), "+f"(c[1]), "+f"(c[2]), "+f"(c[3])
        : "r"(a[0]), "r"(a[1]), "r"(a[2]), "r"(a[3]), "r"(b[0]), "r"(b[1]));
}
__device__ __forceinline__ void cp16(unsigned saddr, const void* gptr) {
    asm volatile("cp.async.cg.shared.global [%0], [%1], 16;"
                 :: "r"(saddr), "l"(gptr) : "memory");
}
__device__ __forceinline__ void cp_commit() {
    asm volatile("cp.async.commit_group;" ::: "memory");
}
template <int N>
__device__ __forceinline__ void cp_wait() {
    asm volatile("cp.async.wait_group %0;" :: "n"(N) : "memory");
}

// ---------------------------------------------------------------------------
// Kernel 0a: w2 (32768 slots) + w1 (3072 slots) -> fp16 MMA B-frag order.
// ---------------------------------------------------------------------------
__global__ void __launch_bounds__(256) prep_kernel(
    const float* __restrict__ w2, const float* __restrict__ w1)
{
    int t = blockIdx.x * 256 + threadIdx.x;
    if (t < 32768) {
        int lane = t & 31;
        int w    = (t >> 5) & 31;
        int kf   = t >> 10;
        int kb   = kf * 16 + (lane & 3) * 2;
        uint4 st;
        unsigned* sp = (unsigned*)&st;
#pragma unroll
        for (int nf = 0; nf < 2; nf++) {
            int j = w * 16 + nf * 8 + (lane >> 2);
            __half2 q0 = __floats2half2_rn(__ldg(w2 + (kb + 0) * NH + j),
                                           __ldg(w2 + (kb + 1) * NH + j));
            __half2 q1 = __floats2half2_rn(__ldg(w2 + (kb + 8) * NH + j),
                                           __ldg(w2 + (kb + 9) * NH + j));
            sp[nf * 2 + 0] = *(unsigned*)&q0;
            sp[nf * 2 + 1] = *(unsigned*)&q1;
        }
        ((uint4*)w2f_frag)[t] = st;
    } else if (t < 32768 + 3072) {
        int t2   = t - 32768;
        int lane = t2 & 31;
        int w    = (t2 >> 5) & 31;
        int kf   = t2 >> 10;                  // 0..2
        int kb   = kf * 16 + (lane & 3) * 2;
        uint4 st;
        unsigned* sp = (unsigned*)&st;
#pragma unroll
        for (int nf = 0; nf < 2; nf++) {
            int j = w * 16 + nf * 8 + (lane >> 2);
            __half2 q0 = __floats2half2_rn(__ldg(w1 + (kb + 0) * NH + j),
                                           __ldg(w1 + (kb + 1) * NH + j));
            __half2 q1 = __floats2half2_rn(__ldg(w1 + (kb + 8) * NH + j),
                                           __ldg(w1 + (kb + 9) * NH + j));
            sp[nf * 2 + 0] = *(unsigned*)&q0;
            sp[nf * 2 + 1] = *(unsigned*)&q1;
        }
        ((uint4*)w1f_frag)[t2] = st;
    }
}

// ---------------------------------------------------------------------------
// Kernel 0b: tabulate G_k(p). 128 blocks x 256 threads, 2 threads/entry.
// ---------------------------------------------------------------------------
__global__ void __launch_bounds__(256) build_tab_kernel(
    const float* __restrict__ mw1, const float* __restrict__ mb1,
    const float* __restrict__ mw2, const float* __restrict__ mb2,
    const float* __restrict__ mw3, const float* __restrict__ mb3)
{
    __shared__ float s_w2[HH * HH];
    __shared__ float s_w1[HH], s_b1[HH], s_b2[HH], s_w3[HH];

    int k  = blockIdx.x >> 3;
    int i  = (blockIdx.x & 7) * 128 + (threadIdx.x >> 1);
    int jh = threadIdx.x & 1;

    {
        const float4* src = (const float4*)(mw2 + k * HH * HH);
        float4* dst = (float4*)s_w2;
        for (int idx = threadIdx.x; idx < HH * HH / 4; idx += 256)
            dst[idx] = src[idx];
    }
    if (threadIdx.x < HH) {
        s_w1[threadIdx.x] = mw1[k * HH + threadIdx.x];
        s_b1[threadIdx.x] = mb1[k * HH + threadIdx.x];
        s_b2[threadIdx.x] = mb2[k * HH + threadIdx.x];
        s_w3[threadIdx.x] = mw3[k * HH + threadIdx.x];
    }
    __syncthreads();

    float p = -PMAXF + (2.f * PMAXF / (NT - 1)) * (float)i;

    float h1v[HH];
#pragma unroll
    for (int h = 0; h < HH; h++)
        h1v[h] = tanhf(fmaf(p, s_w1[h], s_b1[h]));

    float z = 0.f;
#pragma unroll 2
    for (int jg = 0; jg < 8; jg++) {
        int j0 = jh * 32 + jg * 4;
        unsigned long long accA = pack2(s_b2[j0],     s_b2[j0 + 1]);
        unsigned long long accB = pack2(s_b2[j0 + 2], s_b2[j0 + 3]);
#pragma unroll
        for (int h = 0; h < HH; h++) {
            ulonglong2 w = *(const ulonglong2*)&s_w2[h * HH + j0];
            unsigned long long ad = pack2(h1v[h], h1v[h]);
            fma2(accA, w.x, ad);
            fma2(accB, w.y, ad);
        }
        float2 va = unpack2(accA);
        float2 vb = unpack2(accB);
        z = fmaf(s_w3[j0 + 0], tanhf(va.x), z);
        z = fmaf(s_w3[j0 + 1], tanhf(va.y), z);
        z = fmaf(s_w3[j0 + 2], tanhf(vb.x), z);
        z = fmaf(s_w3[j0 + 3], tanhf(vb.y), z);
    }
    z += __shfl_down_sync(0xffffffffu, z, 1, 2);
    if (jh == 0) {
        z += __ldg(mb3 + k);
        g_tab[k * NT + i] = fmaxf(z, 0.f) + log1pf(expf(-fabsf(z)));
    }
}

// ---------------------------------------------------------------------------
// Kernel 1: fused (mono || layer1-MMA) + layer2 fp16-MMA with cp.async pipe.
// 1024 threads, grid 128. Warps 0-15: xs stage + layer1 MMA (32 cols each!).
// Warps 16-31: mono.
// ---------------------------------------------------------------------------
__global__ void __launch_bounds__(1024) fused_kernel(
    const float* __restrict__ X,  const float* __restrict__ wlin,
    const float* __restrict__ b1, const float* __restrict__ b2,
    const float* __restrict__ w3, const float* __restrict__ b3,
    float* __restrict__ out)
{
    extern __shared__ float sm[];
    uint4*  bstage = (uint4*)sm;                          // [NST][1024] uint4 = 128KB
    __half* a1f    = (__half*)(bstage + NST * 1024);      // [32][ASTR]
    __half* xs_h   = a1f + ROWS * ASTR;                   // [32][XSTR]
    float*  wpart  = (float*)(xs_h + ROWS * XSTR);        // [32][32]
    float*  mono_s = wpart + 32 * 32;                     // [32]

    const int tid  = threadIdx.x;
    const int warp = tid >> 5;
    const int lane = tid & 31;
    const int b0   = blockIdx.x * ROWS;

    // ---- prime B pipeline (fills during mono/layer1) ----
    const uint4* bgm = (const uint4*)w2f_frag + warp * 32 + lane;
    const unsigned bst_u = smem_u32(bstage) + (warp * 32 + lane) * 16;
#pragma unroll
    for (int s = 0; s < NST - 1; s++) {
        cp16(bst_u + s * 16384, bgm + s * 1024);
        cp_commit();
    }

    const int arow  = lane & 15;
    const int acol8 = (lane >> 4) * 8;

    if (warp < 16) {
        // ---- stage x_nm as fp16 row-major [r][i] ----
        for (int idx = tid; idx < ROWS * NMD; idx += 512) {
            int r = idx / NMD, i = idx % NMD;
            xs_h[r * XSTR + i] = __float2half_rn(X[(b0 + r) * INF + KM + i]);
        }
        asm volatile("bar.sync 1, 512;" ::: "memory");

        // ---- layer 1: MMA, warp owns cols [warp*32, warp*32+32) (2 slots) ----
        float acc[2][2][2][4];   // [slot][m][nf][e]
#pragma unroll
        for (int s = 0; s < 2; s++)
#pragma unroll
            for (int m = 0; m < 2; m++)
#pragma unroll
                for (int nf = 0; nf < 2; nf++)
#pragma unroll
                    for (int e = 0; e < 4; e++) acc[s][m][nf][e] = 0.f;

        const unsigned xs_u = smem_u32(xs_h);
#pragma unroll
        for (int kf = 0; kf < 3; kf++) {
            uint4 bw0 = ((const uint4*)w1f_frag)[kf * 1024 + (2 * warp) * 32 + lane];
            uint4 bw1 = ((const uint4*)w1f_frag)[kf * 1024 + (2 * warp + 1) * 32 + lane];
            unsigned bfr[2][2][2] = {{{bw0.x, bw0.y}, {bw0.z, bw0.w}},
                                     {{bw1.x, bw1.y}, {bw1.z, bw1.w}}};
            unsigned a[2][4];
#pragma unroll
            for (int m = 0; m < 2; m++) {
                unsigned off = ((m * 16 + arow) * XSTR + kf * 16 + acol8) * 2;
                ldsm_x4(a[m][0], a[m][1], a[m][2], a[m][3], xs_u + off);
            }
#pragma unroll
            for (int s = 0; s < 2; s++)
#pragma unroll
                for (int m = 0; m < 2; m++)
#pragma unroll
                    for (int nf = 0; nf < 2; nf++)
                        mma_f16(acc[s][m][nf], a[m], bfr[s][nf]);
        }
        // epilogue: bias + relu -> a1f (half2 stores), 32 cols per warp
#pragma unroll
        for (int s = 0; s < 2; s++)
#pragma unroll
            for (int m = 0; m < 2; m++)
#pragma unroll
                for (int nf = 0; nf < 2; nf++) {
                    int j  = (2 * warp + s) * 16 + nf * 8 + (lane & 3) * 2;
                    int r0 = m * 16 + (lane >> 2);
                    float2 bv = *(const float2*)(b1 + j);
                    __half2 lo = __floats2half2_rn(fmaxf(acc[s][m][nf][0] + bv.x, 0.f),
                                                   fmaxf(acc[s][m][nf][1] + bv.y, 0.f));
                    __half2 hi = __floats2half2_rn(fmaxf(acc[s][m][nf][2] + bv.x, 0.f),
                                                   fmaxf(acc[s][m][nf][3] + bv.y, 0.f));
                    *(__half2*)(a1f + r0 * ASTR + j)       = lo;
                    *(__half2*)(a1f + (r0 + 8) * ASTR + j) = hi;
                }
    } else {
        // ---- mono term (warps 16-31): one (row, k) per thread ----
        int t2 = tid - 512;
        int r  = t2 >> 4;
        int kk = t2 & 15;
        const float scale = (float)(NT - 1) / (2.f * PMAXF);
        float x = __ldg(X + (b0 + r) * INF + kk);
        const float* tk = g_tab + kk * NT;
        float acc = 0.f;
#pragma unroll
        for (int s = 0; s < SQ; s++) {
            float t = (float)s * (1.f / (SQ - 1));
            float f = (x * t + PMAXF) * scale;
            f = fminf(fmaxf(f, 0.f), (float)(NT - 1) - 1e-3f);
            int i0 = (int)f;
            float fr = f - (float)i0;
            float g0 = tk[i0];
            float g1 = tk[i0 + 1];
            acc += fmaf(fr, g1 - g0, g0);
        }
        float part = acc * (1.f / SQ) * x * __ldg(wlin + kk);
#pragma unroll
        for (int off = 8; off; off >>= 1)
            part += __shfl_down_sync(0xffffffffu, part, off, 16);
        if ((t2 & 15) == 0) mono_s[r] = part;
    }
    __syncthreads();

    // ---- layer 2: fp16 MMA; B smem ring double-buffered into registers ----
    {
        float acc[2][2][4];
#pragma unroll
        for (int m = 0; m < 2; m++)
#pragma unroll
            for (int nf = 0; nf < 2; nf++)
#pragma unroll
                for (int e = 0; e < 4; e++) acc[m][nf][e] = 0.f;

        const unsigned a1_u = smem_u32(a1f);
        const uint4* bsm = bstage + warp * 32 + lane;

        unsigned a[2][2][4];
#pragma unroll
        for (int m = 0; m < 2; m++) {
            unsigned off = ((m * 16 + arow) * ASTR + acol8) * 2;
            ldsm_x4(a[0][m][0], a[0][m][1], a[0][m][2], a[0][m][3], a1_u + off);
        }
        cp_wait<NST - 2>();                 // stage 0 ready
        uint4 bq = bsm[0];

        for (int kf = 0; kf < 32; kf++) {
            int cur = kf & 1, nxt = cur ^ 1;
            int sl = kf + NST - 1;
            if (sl < 32) cp16(bst_u + (sl & (NST - 1)) * 16384, bgm + sl * 1024);
            cp_commit();
            if (kf + 1 < 32) {
#pragma unroll
                for (int m = 0; m < 2; m++) {
                    unsigned off = ((m * 16 + arow) * ASTR + (kf + 1) * 16 + acol8) * 2;
                    ldsm_x4(a[nxt][m][0], a[nxt][m][1], a[nxt][m][2], a[nxt][m][3],
                            a1_u + off);
                }
            }
            unsigned bfr[2][2] = {{bq.x, bq.y}, {bq.z, bq.w}};
            cp_wait<NST - 2>();
            if (kf + 1 < 32) bq = bsm[((kf + 1) & (NST - 1)) * 1024];
#pragma unroll
            for (int m = 0; m < 2; m++)
#pragma unroll
                for (int nf = 0; nf < 2; nf++)
                    mma_f16(acc[m][nf], a[cur][m], bfr[nf]);
        }

        // epilogue: relu(acc + b2) . w3 -> per-row partials (16-col slice)
#pragma unroll
        for (int m = 0; m < 2; m++) {
            float p0 = 0.f, p1 = 0.f;
#pragma unroll
            for (int nf = 0; nf < 2; nf++) {
                int col = warp * 16 + nf * 8 + (lane & 3) * 2;
                float2 b2v = *(const float2*)(b2 + col);
                float2 w3v = *(const float2*)(w3 + col);
                p0 = fmaf(fmaxf(acc[m][nf][0] + b2v.x, 0.f), w3v.x, p0);
                p0 = fmaf(fmaxf(acc[m][nf][1] + b2v.y, 0.f), w3v.y, p0);
                p1 = fmaf(fmaxf(acc[m][nf][2] + b2v.x, 0.f), w3v.x, p1);
                p1 = fmaf(fmaxf(acc[m][nf][3] + b2v.y, 0.f), w3v.y, p1);
            }
            p0 += __shfl_xor_sync(0xffffffffu, p0, 1);
            p0 += __shfl_xor_sync(0xffffffffu, p0, 2);
            p1 += __shfl_xor_sync(0xffffffffu, p1, 1);
            p1 += __shfl_xor_sync(0xffffffffu, p1, 2);
            if ((lane & 3) == 0) {
                int r0 = m * 16 + (lane >> 2);
                wpart[warp * 32 + r0]     = p0;
                wpart[warp * 32 + r0 + 8] = p1;
            }
        }
    }
    __syncthreads();

    // ---- final: sum 32 warp slices + bias + mono ----
    if (tid < ROWS) {
        float s = 0.f;
#pragma unroll
        for (int w = 0; w < 32; w++) s += wpart[w * 32 + tid];
        out[b0 + tid] = s + __ldg(b3) + mono_s[tid];
    }
}

// ---------------------------------------------------------------------------
extern "C" void kernel_launch(void* const* d_in, const int* in_sizes, int n_in,
                              void* d_out, int out_size)
{
    const float* x    = (const float*)d_in[0];
    const float* mw1  = (const float*)d_in[1];
    const float* mb1  = (const float*)d_in[2];
    const float* mw2  = (const float*)d_in[3];
    const float* mb2  = (const float*)d_in[4];
    const float* mw3  = (const float*)d_in[5];
    const float* mb3  = (const float*)d_in[6];
    const float* wlin = (const float*)d_in[7];
    const float* nw1  = (const float*)d_in[8];
    const float* nb1  = (const float*)d_in[9];
    const float* nw2  = (const float*)d_in[10];
    const float* nb2  = (const float*)d_in[11];
    const float* nw3  = (const float*)d_in[12];
    const float* nb3  = (const float*)d_in[13];
    float* out = (float*)d_out;

    int smem = NST * 1024 * 16
             + (ROWS * ASTR + ROWS * XSTR) * (int)sizeof(__half)
             + (32 * 32 + 32) * (int)sizeof(float);   // ~168.3 KB
    cudaFuncSetAttribute(fused_kernel, cudaFuncAttributeMaxDynamicSharedMemorySize, smem);

    prep_kernel<<<140, 256>>>(nw2, nw1);
    build_tab_kernel<<<KM * 8, 256>>>(mw1, mb1, mw2, mb2, mw3, mb3);
    fused_kernel<<<B_ / ROWS, 1024, smem>>>(x, wlin, nb1, nb2, nw3, nb3, out);
}